// round 16
// baseline (speedup 1.0000x reference)
#include <cuda_runtime.h>
#include <cuda_bf16.h>
#include <cuda_fp16.h>
#include <math.h>
#include <stdint.h>

#define Bx 128
#define Lx 256
#define HIDx 768
#define HID2x 1536
#define CDIMx 192
#define SDIMx 128
#define NPROJx 128
#define FDIMx 321
#define BIGF 1000000000.0f

// ---------------- scratch ----------------
__device__ float g_rep[Bx * HID2x];
__device__ float g_Pt[(size_t)Bx * NPROJx * Lx];    // [b][p][l]
__device__ float g_feat[Bx * FDIMx];                // only col 320 (d_ot) used
__device__ float g_partial[32 * Bx * 320];          // split-K partials (z=32)
__device__ int   g_mcnt[Bx];
__device__ unsigned short g_ph[NPROJx * HIDx];      // proj as fp16
__device__ int   g_done;                            // producer-completion counter

// ---------------- helpers ----------------
__device__ __forceinline__ uint32_t smem_u32(const void* p) {
    uint32_t a;
    asm("{ .reg .u64 t; cvta.to.shared.u64 t, %1; cvt.u32.u64 %0, t; }" : "=r"(a) : "l"(p));
    return a;
}

__device__ __forceinline__ uint2 cvt4_f16(float4 v) {
    uint32_t h0, h1;
    asm("cvt.rn.f16x2.f32 %0, %1, %2;" : "=r"(h0) : "f"(v.y), "f"(v.x));
    asm("cvt.rn.f16x2.f32 %0, %1, %2;" : "=r"(h1) : "f"(v.w), "f"(v.z));
    return make_uint2(h0, h1);
}

#define LDSM4(R0, R1, R2, R3, ADDR) \
    asm volatile("ldmatrix.sync.aligned.m8n8.x4.shared.b16 {%0,%1,%2,%3}, [%4];" \
        : "=r"(R0), "=r"(R1), "=r"(R2), "=r"(R3) : "r"(ADDR))

#define MMA_F16(D, A, B) \
    asm volatile("mma.sync.aligned.m16n8k16.row.col.f32.f16.f16.f32 " \
        "{%0,%1,%2,%3}, {%4,%5,%6,%7}, {%8,%9}, {%0,%1,%2,%3};" \
        : "+f"((D)[0]), "+f"((D)[1]), "+f"((D)[2]), "+f"((D)[3]) \
        : "r"((A)[0]), "r"((A)[1]), "r"((A)[2]), "r"((A)[3]), \
          "r"((B)[0]), "r"((B)[1]))

// ===== K1: 512 threads, l-split, 4-acc ILP; gridDim.y==3 slice does proj cvt =====
__global__ void __launch_bounds__(512) k1_stats(const float* __restrict__ H,
                                                const int* __restrict__ tt,
                                                const int* __restrict__ m,
                                                const float* __restrict__ proj) {
    int b = blockIdx.x;
    int c = blockIdx.y;   // 0..2 = h-chunks; 3 = proj conversion slice
    int tid = threadIdx.x;

    if (c == 3) {
        if (b == 0 && tid == 0) g_done = 0;   // reset pipeline counter for k34
        int i = b * 512 + tid;
        if (i < (NPROJx * HIDx / 4)) {
            float4 v = reinterpret_cast<const float4*>(proj)[i];
            reinterpret_cast<uint2*>(g_ph)[i] = cvt4_f16(v);
        }
        return;
    }

    __shared__ float sf0[Lx], sf1[Lx];
    __shared__ float ps[2][2][256];
    __shared__ float sc0, sc1;

    int hl = tid & 255;
    int lh = tid >> 8;     // 0/1: which l-half

    if (tid < 256) {
        int t = tt[b * Lx + tid];
        int mm = m[b * Lx + tid];
        sf0[tid] = (t == 0 && mm == 1) ? 1.f : 0.f;
        sf1[tid] = (t == 1 && mm == 1) ? 1.f : 0.f;
    }
    __syncthreads();

    if (tid == 0) {
        int c0 = 0, c1 = 0;
        for (int l = 0; l < Lx; l++) { c0 += (sf0[l] > 0.5f); c1 += (sf1[l] > 0.5f); }
        if (c == 0) {
            g_mcnt[b] = min(c0, c1);
            g_feat[b * FDIMx + 320] = 0.f;
        }
        sc0 = fmaxf((float)c0, 1.f);
        sc1 = fmaxf((float)c1, 1.f);
    }

    int h = c * 256 + hl;
    const float* Hb = H + (size_t)b * Lx * HIDx;
    const float* Hp = Hb + (size_t)(lh * 128) * HIDx + h;
    const float* f0p = sf0 + lh * 128;
    const float* f1p = sf1 + lh * 128;

    float a0 = 0.f, a1 = 0.f, a2 = 0.f, a3 = 0.f;
    float b0 = 0.f, b1 = 0.f, b2 = 0.f, b3 = 0.f;
#pragma unroll 8
    for (int l = 0; l < 128; l += 4) {
        float v0 = Hp[(size_t)(l + 0) * HIDx];
        float v1 = Hp[(size_t)(l + 1) * HIDx];
        float v2 = Hp[(size_t)(l + 2) * HIDx];
        float v3 = Hp[(size_t)(l + 3) * HIDx];
        a0 += f0p[l + 0] * v0; b0 += f1p[l + 0] * v0;
        a1 += f0p[l + 1] * v1; b1 += f1p[l + 1] * v1;
        a2 += f0p[l + 2] * v2; b2 += f1p[l + 2] * v2;
        a3 += f0p[l + 3] * v3; b3 += f1p[l + 3] * v3;
    }
    ps[0][lh][hl] = (a0 + a1) + (a2 + a3);
    ps[1][lh][hl] = (b0 + b1) + (b2 + b3);
    __syncthreads();

    if (tid < 256) {
        float s0 = ps[0][0][hl] + ps[0][1][hl];
        float s1 = ps[1][0][hl] + ps[1][1][hl];
        g_rep[(size_t)b * HID2x + h]        = Hb[h];
        g_rep[(size_t)b * HID2x + HIDx + h] = s0 / sc0 - s1 / sc1;
    }
}

// ============ K2 (fp16 HMMA single-pass, fused cvt, 128lx128p) ============
#define K2_SMEM 32768

__global__ void __launch_bounds__(256, 2) k2_hmma(const float* __restrict__ H) {
    extern __shared__ char sm[];
    uint32_t sb = smem_u32(sm);
    int b = blockIdx.x;
    int l0 = blockIdx.y * 128;
    int tid = threadIdx.x;
    int lane = tid & 31, w = tid >> 5;
    int wm = w >> 2;
    int wn = w & 3;

    int srow = tid >> 1;
    int half = tid & 1;
    const float4* gA = reinterpret_cast<const float4*>(H + ((size_t)(b * Lx) + l0 + srow) * HIDx) + half * 4;
    const uint4* gB = reinterpret_cast<const uint4*>(g_ph + (size_t)srow * HIDx) + half * 2;
    int sw_s = (srow >> 1) & 3;
    uint32_t o0 = (uint32_t)srow * 64 + (uint32_t)(((half * 2)     ^ sw_s) * 16);
    uint32_t o1 = (uint32_t)srow * 64 + (uint32_t)(((half * 2 + 1) ^ sw_s) * 16);

    uint32_t rowA[4]; uint32_t swA[4];
#pragma unroll
    for (int i = 0; i < 4; i++) {
        int r = wm * 64 + i * 16 + (lane & 15);
        rowA[i] = (uint32_t)r * 64;
        swA[i] = (uint32_t)((r >> 1) & 3);
    }
    uint32_t ua = (uint32_t)(lane >> 4);
    uint32_t rowB[2]; uint32_t swB[2];
#pragma unroll
    for (int j2 = 0; j2 < 2; j2++) {
        int r = wn * 32 + j2 * 16 + (lane & 7) + ((lane >> 4) << 3);
        rowB[j2] = (uint32_t)r * 64;
        swB[j2] = (uint32_t)((r >> 1) & 3);
    }
    uint32_t ub = (uint32_t)((lane >> 3) & 1);

    float acc[4][4][4];
#pragma unroll
    for (int i = 0; i < 4; i++)
#pragma unroll
        for (int j = 0; j < 4; j++)
#pragma unroll
            for (int r = 0; r < 4; r++) acc[i][j][r] = 0.f;

    float4 pfA[4];
    uint4 pfB[2];
    {
#pragma unroll
        for (int q = 0; q < 4; q++) pfA[q] = gA[q];
        pfB[0] = gB[0]; pfB[1] = gB[1];
        char* sp = sm;
        uint2 a0 = cvt4_f16(pfA[0]);
        uint2 a1 = cvt4_f16(pfA[1]);
        uint2 a2 = cvt4_f16(pfA[2]);
        uint2 a3 = cvt4_f16(pfA[3]);
        *reinterpret_cast<uint4*>(sp + 0 + o0) = make_uint4(a0.x, a0.y, a1.x, a1.y);
        *reinterpret_cast<uint4*>(sp + 0 + o1) = make_uint4(a2.x, a2.y, a3.x, a3.y);
        *reinterpret_cast<uint4*>(sp + 8192 + o0) = pfB[0];
        *reinterpret_cast<uint4*>(sp + 8192 + o1) = pfB[1];
    }
    __syncthreads();

    for (int c = 0; c < 24; c++) {
        int buf = c & 1;
        if (c < 23) {
            int offA = (c + 1) * 8;
            int offB = (c + 1) * 4;
#pragma unroll
            for (int q = 0; q < 4; q++) pfA[q] = gA[offA + q];
            pfB[0] = gB[offB]; pfB[1] = gB[offB + 1];
        }

        uint32_t bb = sb + (uint32_t)buf * 16384;
#pragma unroll
        for (int sel = 0; sel < 2; sel++) {
            uint32_t u2 = (uint32_t)(sel * 2);
            uint32_t bf[4][2];
#pragma unroll
            for (int j2 = 0; j2 < 2; j2++) {
                uint32_t ah = bb + 8192 + rowB[j2] + (((u2 + ub) ^ swB[j2]) << 4);
                uint32_t r0, r1, r2, r3;
                LDSM4(r0, r1, r2, r3, ah);
                bf[j2 * 2][0] = r0; bf[j2 * 2][1] = r1;
                bf[j2 * 2 + 1][0] = r2; bf[j2 * 2 + 1][1] = r3;
            }
            uint32_t af[4][4];
#pragma unroll
            for (int i = 0; i < 4; i++) {
                uint32_t a = bb + rowA[i] + (((u2 + ua) ^ swA[i]) << 4);
                LDSM4(af[i][0], af[i][1], af[i][2], af[i][3], a);
            }
#pragma unroll
            for (int i = 0; i < 4; i++)
#pragma unroll
                for (int j = 0; j < 4; j++) {
                    MMA_F16(acc[i][j], af[i], bf[j]);
                }
        }

        if (c < 23) {
            char* sp = sm + (1 - buf) * 16384;
            uint2 a0 = cvt4_f16(pfA[0]);
            uint2 a1 = cvt4_f16(pfA[1]);
            uint2 a2 = cvt4_f16(pfA[2]);
            uint2 a3 = cvt4_f16(pfA[3]);
            *reinterpret_cast<uint4*>(sp + 0 + o0) = make_uint4(a0.x, a0.y, a1.x, a1.y);
            *reinterpret_cast<uint4*>(sp + 0 + o1) = make_uint4(a2.x, a2.y, a3.x, a3.y);
            *reinterpret_cast<uint4*>(sp + 8192 + o0) = pfB[0];
            *reinterpret_cast<uint4*>(sp + 8192 + o1) = pfB[1];
        }
        __syncthreads();
    }

    float* gp = g_Pt + (size_t)b * NPROJx * Lx + l0;
#pragma unroll
    for (int i = 0; i < 4; i++) {
        int lrow = wm * 64 + i * 16 + (lane >> 2);
#pragma unroll
        for (int j = 0; j < 4; j++) {
            int p = wn * 32 + j * 8 + (lane & 3) * 2;
            gp[(size_t)p * Lx + lrow]           = acc[i][j][0];
            gp[(size_t)(p + 1) * Lx + lrow]     = acc[i][j][1];
            gp[(size_t)p * Lx + lrow + 8]       = acc[i][j][2];
            gp[(size_t)(p + 1) * Lx + lrow + 8] = acc[i][j][3];
        }
    }
}

// ===== sort helpers (contiguous-run bitonic) =====
__device__ __forceinline__ void cexA(float& a, float& b) {
    float mn = fminf(a, b);
    b = fmaxf(a, b);
    a = mn;
}
__device__ __forceinline__ void cexD(float& a, float& b) {
    float mx = fmaxf(a, b);
    b = fminf(a, b);
    a = mx;
}
__device__ __forceinline__ void cexP(float& a, float& b, bool asc) {
    float mn = asc ? fminf(a, b) : fmaxf(a, b);
    float mx = asc ? fmaxf(a, b) : fminf(a, b);
    a = mn; b = mx;
}
__device__ __forceinline__ void merge8(float v[8], bool asc) {
    cexP(v[0], v[4], asc); cexP(v[1], v[5], asc); cexP(v[2], v[6], asc); cexP(v[3], v[7], asc);
    cexP(v[0], v[2], asc); cexP(v[1], v[3], asc); cexP(v[4], v[6], asc); cexP(v[5], v[7], asc);
    cexP(v[0], v[1], asc); cexP(v[2], v[3], asc); cexP(v[4], v[5], asc); cexP(v[6], v[7], asc);
}
__device__ __forceinline__ void cross8(float v[8], int s, bool keepmin) {
#pragma unroll
    for (int r = 0; r < 8; r++) {
        float o = __shfl_xor_sync(0xffffffffu, v[r], s);
        v[r] = keepmin ? fminf(v[r], o) : fmaxf(v[r], o);
    }
}
__device__ __forceinline__ void sort256v2(float v[8], int lane) {
    cexA(v[0], v[1]); cexD(v[2], v[3]); cexA(v[4], v[5]); cexD(v[6], v[7]);
    cexA(v[0], v[2]); cexA(v[1], v[3]); cexD(v[4], v[6]); cexD(v[5], v[7]);
    cexA(v[0], v[1]); cexA(v[2], v[3]); cexD(v[4], v[5]); cexD(v[6], v[7]);
    bool a8 = (lane & 1) == 0;
    merge8(v, a8);
    bool a16 = (lane & 2) == 0;
    cross8(v, 1, ((lane & 1) == 0) == a16);
    merge8(v, a16);
    bool a32 = (lane & 4) == 0;
    cross8(v, 2, ((lane & 2) == 0) == a32);
    cross8(v, 1, ((lane & 1) == 0) == a32);
    merge8(v, a32);
    bool a64 = (lane & 8) == 0;
    cross8(v, 4, ((lane & 4) == 0) == a64);
    cross8(v, 2, ((lane & 2) == 0) == a64);
    cross8(v, 1, ((lane & 1) == 0) == a64);
    merge8(v, a64);
    bool a128 = (lane & 16) == 0;
    cross8(v, 8, ((lane & 8) == 0) == a128);
    cross8(v, 4, ((lane & 4) == 0) == a128);
    cross8(v, 2, ((lane & 2) == 0) == a128);
    cross8(v, 1, ((lane & 1) == 0) == a128);
    merge8(v, a128);
    cross8(v, 16, (lane & 16) == 0);
    cross8(v, 8,  (lane & 8) == 0);
    cross8(v, 4,  (lane & 4) == 0);
    cross8(v, 2,  (lane & 2) == 0);
    cross8(v, 1,  (lane & 1) == 0);
    merge8(v, true);
}

__device__ __forceinline__ float2 blockReduceSum2_256(float2 val, float2* sbuf) {
    int tid = threadIdx.x;
#pragma unroll
    for (int o = 16; o > 0; o >>= 1) {
        val.x += __shfl_down_sync(0xffffffffu, val.x, o);
        val.y += __shfl_down_sync(0xffffffffu, val.y, o);
    }
    if ((tid & 31) == 0) sbuf[tid >> 5] = val;
    __syncthreads();
    if (tid < 32) {
        float2 r = (tid < 8) ? sbuf[tid] : make_float2(0.f, 0.f);
#pragma unroll
        for (int o = 4; o > 0; o >>= 1) {
            r.x += __shfl_down_sync(0xffffffffu, r.x, o);
            r.y += __shfl_down_sync(0xffffffffu, r.y, o);
        }
        if (tid == 0) sbuf[32] = r;
    }
    __syncthreads();
    float2 out = sbuf[32];
    __syncthreads();
    return out;
}

// ===== FK: k4a (0..639) + k3 (640..2687) + k5 (2688..2815, spin-gated) =====
#define FK_SMEM 18432
#define NPROD 2688

__global__ void __launch_bounds__(256) k345_fused(const int* __restrict__ tt,
                                                  const int* __restrict__ m,
                                                  const float* __restrict__ Wc,
                                                  const float* __restrict__ Ws,
                                                  const float* __restrict__ bc,
                                                  const float* __restrict__ bs,
                                                  const float* __restrict__ gate,
                                                  const float* __restrict__ ln_g,
                                                  const float* __restrict__ ln_b,
                                                  const float* __restrict__ Wcls,
                                                  const float* __restrict__ bcls,
                                                  float* __restrict__ out) {
    extern __shared__ char dyn[];
    int tid = threadIdx.x;

    if (blockIdx.x < 640) {
        // ---------------- k4a: feature GEMM role ----------------
        int idx = blockIdx.x;
        int ftile = (idx % 5) * 64;
        int btile = ((idx / 5) & 3) * 32;
        int kc    = (idx / 20) * 48;

        float* repS = reinterpret_cast<float*>(dyn);
        float* wS   = repS + 48 * 32;

        int tx = tid & 15;
        int ty = tid >> 4;

#pragma unroll
        for (int s = 0; s < 3; s++) {
#pragma unroll
            for (int q = 0; q < 2; q++) {
                int e = tid + q * 256;
                int kk = e & 15, bb = e >> 4;
                repS[(s * 16 + kk) * 32 + bb] = g_rep[(size_t)(btile + bb) * HID2x + kc + s * 16 + kk];
            }
#pragma unroll
            for (int q = 0; q < 4; q++) {
                int e = tid + q * 256;
                int kk = e & 15, ff = e >> 4;
                int f = ftile + ff;
                const float* Wr = (f < CDIMx) ? (Wc + (size_t)f * HID2x)
                                              : (Ws + (size_t)(f - CDIMx) * HID2x);
                wS[(s * 16 + kk) * 64 + ff] = Wr[kc + s * 16 + kk];
            }
        }
        __syncthreads();

        float acc[2][4];
#pragma unroll
        for (int i = 0; i < 2; i++)
#pragma unroll
            for (int j = 0; j < 4; j++) acc[i][j] = 0.f;

#pragma unroll 8
        for (int kk = 0; kk < 48; kk++) {
            float4 wv = *reinterpret_cast<const float4*>(&wS[kk * 64 + tx * 4]);
            float r0 = repS[kk * 32 + ty * 2];
            float r1 = repS[kk * 32 + ty * 2 + 1];
            acc[0][0] += r0 * wv.x; acc[0][1] += r0 * wv.y;
            acc[0][2] += r0 * wv.z; acc[0][3] += r0 * wv.w;
            acc[1][0] += r1 * wv.x; acc[1][1] += r1 * wv.y;
            acc[1][2] += r1 * wv.z; acc[1][3] += r1 * wv.w;
        }

        int z = idx / 20;
#pragma unroll
        for (int i = 0; i < 2; i++) {
            int bb = btile + ty * 2 + i;
            float4 o = make_float4(acc[i][0], acc[i][1], acc[i][2], acc[i][3]);
            *reinterpret_cast<float4*>(&g_partial[((size_t)z * Bx + bb) * 320 + ftile + tx * 4]) = o;
        }
        __threadfence();
        __syncthreads();
        if (tid == 0) atomicAdd(&g_done, 1);
    } else if (blockIdx.x < NPROD) {
        // ---------------- k3: sort role ----------------
        int bid = blockIdx.x - 640;
        int b = bid >> 4;
        int px = bid & 15;
        int warp = tid >> 5, lane = tid & 31;
        float* sgrp = reinterpret_cast<float*>(dyn);

        int p = px * 8 + warp;
        const float* col = g_Pt + ((size_t)b * NPROJx + p) * Lx;

        float4 va = reinterpret_cast<const float4*>(col)[lane * 2];
        float4 vb = reinterpret_cast<const float4*>(col)[lane * 2 + 1];
        int4 ta = reinterpret_cast<const int4*>(tt + b * Lx)[lane * 2];
        int4 tb = reinterpret_cast<const int4*>(tt + b * Lx)[lane * 2 + 1];
        int4 ma = reinterpret_cast<const int4*>(m + b * Lx)[lane * 2];
        int4 mb = reinterpret_cast<const int4*>(m + b * Lx)[lane * 2 + 1];

        float raw[8] = {va.x, va.y, va.z, va.w, vb.x, vb.y, vb.z, vb.w};
        int tvs[8] = {ta.x, ta.y, ta.z, ta.w, tb.x, tb.y, tb.z, tb.w};
        int mvs[8] = {ma.x, ma.y, ma.z, ma.w, mb.x, mb.y, mb.z, mb.w};

        float v[8];
#pragma unroll
        for (int r = 0; r < 8; r++) {
            int tg = (mvs[r] == 1) ? tvs[r] : 2;
            float base = (tg == 2) ? BIGF : raw[r];
            uint32_t u = (__float_as_uint(base) & ~1u) | (uint32_t)(tg != 0);
            v[r] = __uint_as_float(u);
        }
        sort256v2(v, lane);

        int g[8];
        int cl = 0;
#pragma unroll
        for (int r = 0; r < 8; r++) {
            g[r] = (int)(__float_as_uint(v[r]) & 1u);
            cl += g[r];
        }
        int inc = cl;
#pragma unroll
        for (int o = 1; o < 32; o <<= 1) {
            int n = __shfl_up_sync(0xffffffffu, inc, o);
            if (lane >= o) inc += n;
        }
        int c1 = inc - cl;

        float* s0 = sgrp + warp * 512;
        float* s1 = s0 + 256;
#pragma unroll
        for (int r = 0; r < 8; r++) {
            float val = __uint_as_float(__float_as_uint(v[r]) & ~1u);
            int idx = lane * 8 + r;
            if (g[r]) { s1[c1] = val; c1++; }
            else      { s0[idx - c1] = val; }
        }
        __syncwarp();

        int mc = g_mcnt[b];
        float s = 0.f;
#pragma unroll
        for (int r = 0; r < 8; r++) {
            int i = r * 32 + lane;
            if (i < mc) s += fabsf(s0[i] - s1[i]);
        }
#pragma unroll
        for (int o = 16; o > 0; o >>= 1) s += __shfl_down_sync(0xffffffffu, s, o);

        if (lane == 0) {
            float mean = s / (float)max(mc, 1);
            atomicMax(reinterpret_cast<int*>(&g_feat[b * FDIMx + 320]), __float_as_int(mean));
        }
        __threadfence();
        __syncthreads();
        if (tid == 0) atomicAdd(&g_done, 1);
    } else {
        // ---------------- k5 role: wait for all producers, then LN + classifier ----------------
        int b = blockIdx.x - NPROD;
        float2* sbuf = reinterpret_cast<float2*>(dyn);

        if (tid == 0) {
            volatile int* dp = &g_done;
            while (*dp < NPROD) { }
        }
        __syncthreads();
        __threadfence();

        float gv = 1.f / (1.f + expf(-gate[0]));

        // f1 = tid (0..255, always < 320); f2 = tid + 256 (256..511, active <= 320)
        int f1 = tid;
        int f2 = tid + 256;
        float x1 = 0.f, x2 = 0.f;
        {
            float s = 0.f;
#pragma unroll
            for (int z = 0; z < 32; z++) s += g_partial[((size_t)z * Bx + b) * 320 + f1];
            if (f1 < CDIMx) x1 = (s + bc[f1]) * (1.f - gv);
            else            x1 = (s + bs[f1 - CDIMx]) * gv;
        }
        if (f2 < 320) {
            float s = 0.f;
#pragma unroll
            for (int z = 0; z < 32; z++) s += g_partial[((size_t)z * Bx + b) * 320 + f2];
            x2 = (s + bs[f2 - CDIMx]) * gv;
        } else if (f2 == 320) {
            x2 = g_feat[b * FDIMx + 320];
        }

        float2 ss = blockReduceSum2_256(make_float2(x1 + x2, x1 * x1 + x2 * x2), sbuf);
        float mean = ss.x / (float)FDIMx;
        float var  = ss.y / (float)FDIMx - mean * mean;
        float inv  = rsqrtf(var + 1e-5f);

        float nrm1 = (x1 - mean) * inv * ln_g[f1] + ln_b[f1];
        float c0 = nrm1 * Wcls[f1];
        float c1v = nrm1 * Wcls[FDIMx + f1];
        if (f2 <= 320) {
            float nrm2 = (x2 - mean) * inv * ln_g[f2] + ln_b[f2];
            c0 += nrm2 * Wcls[f2];
            c1v += nrm2 * Wcls[FDIMx + f2];
        }

        float2 cls = blockReduceSum2_256(make_float2(c0, c1v), sbuf);
        if (tid == 0) {
            out[b * 2 + 0] = cls.x + bcls[0];
            out[b * 2 + 1] = cls.y + bcls[1];
        }
    }
}

// =================================== launch ======================================
extern "C" void kernel_launch(void* const* d_in, const int* in_sizes, int n_in,
                              void* d_out, int out_size) {
    const float* H    = (const float*)d_in[0];
    const int*   tt   = (const int*)d_in[1];
    const int*   m    = (const int*)d_in[2];
    const float* Wc   = (const float*)d_in[3];
    const float* bc   = (const float*)d_in[4];
    const float* Ws   = (const float*)d_in[5];
    const float* bs   = (const float*)d_in[6];
    const float* gate = (const float*)d_in[7];
    const float* ln_g = (const float*)d_in[8];
    const float* ln_b = (const float*)d_in[9];
    const float* Wcls = (const float*)d_in[10];
    const float* bcls = (const float*)d_in[11];
    const float* proj = (const float*)d_in[12];
    float* out = (float*)d_out;

    cudaFuncSetAttribute(k2_hmma, cudaFuncAttributeMaxDynamicSharedMemorySize, K2_SMEM);

    k1_stats<<<dim3(Bx, 4), 512>>>(H, tt, m, proj);
    k2_hmma<<<dim3(Bx, 2), 256, K2_SMEM>>>(H);
    k345_fused<<<2816, 256, FK_SMEM>>>(tt, m, Wc, Ws, bc, bs, gate,
                                       ln_g, ln_b, Wcls, bcls, out);
}

// round 17
// speedup vs baseline: 1.1384x; 1.1384x over previous
#include <cuda_runtime.h>
#include <cuda_bf16.h>
#include <cuda_fp16.h>
#include <math.h>
#include <stdint.h>

#define Bx 128
#define Lx 256
#define HIDx 768
#define HID2x 1536
#define CDIMx 192
#define SDIMx 128
#define NPROJx 128
#define FDIMx 321
#define BIGF 1000000000.0f

// ---------------- scratch ----------------
__device__ float g_rep[Bx * HID2x];
__device__ float g_Pt[(size_t)Bx * NPROJx * Lx];    // [b][p][l]
__device__ float g_feat[Bx * FDIMx];                // only col 320 (d_ot) used
__device__ float g_partial[32 * Bx * 320];          // split-K partials (z=32)
__device__ unsigned short g_ph[NPROJx * HIDx];      // proj as fp16
__device__ int   g_done;                            // k3+k4a completion counter
__device__ int   g_repdone;                         // k1-role completion counter

// ---------------- helpers ----------------
__device__ __forceinline__ uint32_t smem_u32(const void* p) {
    uint32_t a;
    asm("{ .reg .u64 t; cvta.to.shared.u64 t, %1; cvt.u32.u64 %0, t; }" : "=r"(a) : "l"(p));
    return a;
}

__device__ __forceinline__ uint2 cvt4_f16(float4 v) {
    uint32_t h0, h1;
    asm("cvt.rn.f16x2.f32 %0, %1, %2;" : "=r"(h0) : "f"(v.y), "f"(v.x));
    asm("cvt.rn.f16x2.f32 %0, %1, %2;" : "=r"(h1) : "f"(v.w), "f"(v.z));
    return make_uint2(h0, h1);
}

#define LDSM4(R0, R1, R2, R3, ADDR) \
    asm volatile("ldmatrix.sync.aligned.m8n8.x4.shared.b16 {%0,%1,%2,%3}, [%4];" \
        : "=r"(R0), "=r"(R1), "=r"(R2), "=r"(R3) : "r"(ADDR))

#define MMA_F16(D, A, B) \
    asm volatile("mma.sync.aligned.m16n8k16.row.col.f32.f16.f16.f32 " \
        "{%0,%1,%2,%3}, {%4,%5,%6,%7}, {%8,%9}, {%0,%1,%2,%3};" \
        : "+f"((D)[0]), "+f"((D)[1]), "+f"((D)[2]), "+f"((D)[3]) \
        : "r"((A)[0]), "r"((A)[1]), "r"((A)[2]), "r"((A)[3]), \
          "r"((B)[0]), "r"((B)[1]))

// ===== K0p: proj cvt + counter resets + g_feat d_ot init =====
__global__ void k0_prep(const float* __restrict__ proj) {
    int i = blockIdx.x * 256 + threadIdx.x;
    if (i < (NPROJx * HIDx / 4)) {
        float4 v = reinterpret_cast<const float4*>(proj)[i];
        reinterpret_cast<uint2*>(g_ph)[i] = cvt4_f16(v);
    }
    if (blockIdx.x == 0) {
        if (threadIdx.x == 0) { g_done = 0; g_repdone = 0; }
        if (threadIdx.x < Bx) g_feat[threadIdx.x * FDIMx + 320] = 0.f;
    }
}

// ============ K2 (fp16 HMMA single-pass, fused cvt, 128lx128p) ============
#define K2_SMEM 32768

__global__ void __launch_bounds__(256, 2) k2_hmma(const float* __restrict__ H) {
    extern __shared__ char sm[];
    uint32_t sb = smem_u32(sm);
    int b = blockIdx.x;
    int l0 = blockIdx.y * 128;
    int tid = threadIdx.x;
    int lane = tid & 31, w = tid >> 5;
    int wm = w >> 2;
    int wn = w & 3;

    int srow = tid >> 1;
    int half = tid & 1;
    const float4* gA = reinterpret_cast<const float4*>(H + ((size_t)(b * Lx) + l0 + srow) * HIDx) + half * 4;
    const uint4* gB = reinterpret_cast<const uint4*>(g_ph + (size_t)srow * HIDx) + half * 2;
    int sw_s = (srow >> 1) & 3;
    uint32_t o0 = (uint32_t)srow * 64 + (uint32_t)(((half * 2)     ^ sw_s) * 16);
    uint32_t o1 = (uint32_t)srow * 64 + (uint32_t)(((half * 2 + 1) ^ sw_s) * 16);

    uint32_t rowA[4]; uint32_t swA[4];
#pragma unroll
    for (int i = 0; i < 4; i++) {
        int r = wm * 64 + i * 16 + (lane & 15);
        rowA[i] = (uint32_t)r * 64;
        swA[i] = (uint32_t)((r >> 1) & 3);
    }
    uint32_t ua = (uint32_t)(lane >> 4);
    uint32_t rowB[2]; uint32_t swB[2];
#pragma unroll
    for (int j2 = 0; j2 < 2; j2++) {
        int r = wn * 32 + j2 * 16 + (lane & 7) + ((lane >> 4) << 3);
        rowB[j2] = (uint32_t)r * 64;
        swB[j2] = (uint32_t)((r >> 1) & 3);
    }
    uint32_t ub = (uint32_t)((lane >> 3) & 1);

    float acc[4][4][4];
#pragma unroll
    for (int i = 0; i < 4; i++)
#pragma unroll
        for (int j = 0; j < 4; j++)
#pragma unroll
            for (int r = 0; r < 4; r++) acc[i][j][r] = 0.f;

    float4 pfA[4];
    uint4 pfB[2];
    {
#pragma unroll
        for (int q = 0; q < 4; q++) pfA[q] = gA[q];
        pfB[0] = gB[0]; pfB[1] = gB[1];
        char* sp = sm;
        uint2 a0 = cvt4_f16(pfA[0]);
        uint2 a1 = cvt4_f16(pfA[1]);
        uint2 a2 = cvt4_f16(pfA[2]);
        uint2 a3 = cvt4_f16(pfA[3]);
        *reinterpret_cast<uint4*>(sp + 0 + o0) = make_uint4(a0.x, a0.y, a1.x, a1.y);
        *reinterpret_cast<uint4*>(sp + 0 + o1) = make_uint4(a2.x, a2.y, a3.x, a3.y);
        *reinterpret_cast<uint4*>(sp + 8192 + o0) = pfB[0];
        *reinterpret_cast<uint4*>(sp + 8192 + o1) = pfB[1];
    }
    __syncthreads();

    for (int c = 0; c < 24; c++) {
        int buf = c & 1;
        if (c < 23) {
            int offA = (c + 1) * 8;
            int offB = (c + 1) * 4;
#pragma unroll
            for (int q = 0; q < 4; q++) pfA[q] = gA[offA + q];
            pfB[0] = gB[offB]; pfB[1] = gB[offB + 1];
        }

        uint32_t bb = sb + (uint32_t)buf * 16384;
#pragma unroll
        for (int sel = 0; sel < 2; sel++) {
            uint32_t u2 = (uint32_t)(sel * 2);
            uint32_t bf[4][2];
#pragma unroll
            for (int j2 = 0; j2 < 2; j2++) {
                uint32_t ah = bb + 8192 + rowB[j2] + (((u2 + ub) ^ swB[j2]) << 4);
                uint32_t r0, r1, r2, r3;
                LDSM4(r0, r1, r2, r3, ah);
                bf[j2 * 2][0] = r0; bf[j2 * 2][1] = r1;
                bf[j2 * 2 + 1][0] = r2; bf[j2 * 2 + 1][1] = r3;
            }
            uint32_t af[4][4];
#pragma unroll
            for (int i = 0; i < 4; i++) {
                uint32_t a = bb + rowA[i] + (((u2 + ua) ^ swA[i]) << 4);
                LDSM4(af[i][0], af[i][1], af[i][2], af[i][3], a);
            }
#pragma unroll
            for (int i = 0; i < 4; i++)
#pragma unroll
                for (int j = 0; j < 4; j++) {
                    MMA_F16(acc[i][j], af[i], bf[j]);
                }
        }

        if (c < 23) {
            char* sp = sm + (1 - buf) * 16384;
            uint2 a0 = cvt4_f16(pfA[0]);
            uint2 a1 = cvt4_f16(pfA[1]);
            uint2 a2 = cvt4_f16(pfA[2]);
            uint2 a3 = cvt4_f16(pfA[3]);
            *reinterpret_cast<uint4*>(sp + 0 + o0) = make_uint4(a0.x, a0.y, a1.x, a1.y);
            *reinterpret_cast<uint4*>(sp + 0 + o1) = make_uint4(a2.x, a2.y, a3.x, a3.y);
            *reinterpret_cast<uint4*>(sp + 8192 + o0) = pfB[0];
            *reinterpret_cast<uint4*>(sp + 8192 + o1) = pfB[1];
        }
        __syncthreads();
    }

    float* gp = g_Pt + (size_t)b * NPROJx * Lx + l0;
#pragma unroll
    for (int i = 0; i < 4; i++) {
        int lrow = wm * 64 + i * 16 + (lane >> 2);
#pragma unroll
        for (int j = 0; j < 4; j++) {
            int p = wn * 32 + j * 8 + (lane & 3) * 2;
            gp[(size_t)p * Lx + lrow]           = acc[i][j][0];
            gp[(size_t)(p + 1) * Lx + lrow]     = acc[i][j][1];
            gp[(size_t)p * Lx + lrow + 8]       = acc[i][j][2];
            gp[(size_t)(p + 1) * Lx + lrow + 8] = acc[i][j][3];
        }
    }
}

// ===== sort helpers (contiguous-run bitonic) =====
__device__ __forceinline__ void cexA(float& a, float& b) {
    float mn = fminf(a, b);
    b = fmaxf(a, b);
    a = mn;
}
__device__ __forceinline__ void cexD(float& a, float& b) {
    float mx = fmaxf(a, b);
    b = fminf(a, b);
    a = mx;
}
__device__ __forceinline__ void cexP(float& a, float& b, bool asc) {
    float mn = asc ? fminf(a, b) : fmaxf(a, b);
    float mx = asc ? fmaxf(a, b) : fminf(a, b);
    a = mn; b = mx;
}
__device__ __forceinline__ void merge8(float v[8], bool asc) {
    cexP(v[0], v[4], asc); cexP(v[1], v[5], asc); cexP(v[2], v[6], asc); cexP(v[3], v[7], asc);
    cexP(v[0], v[2], asc); cexP(v[1], v[3], asc); cexP(v[4], v[6], asc); cexP(v[5], v[7], asc);
    cexP(v[0], v[1], asc); cexP(v[2], v[3], asc); cexP(v[4], v[5], asc); cexP(v[6], v[7], asc);
}
__device__ __forceinline__ void cross8(float v[8], int s, bool keepmin) {
#pragma unroll
    for (int r = 0; r < 8; r++) {
        float o = __shfl_xor_sync(0xffffffffu, v[r], s);
        v[r] = keepmin ? fminf(v[r], o) : fmaxf(v[r], o);
    }
}
__device__ __forceinline__ void sort256v2(float v[8], int lane) {
    cexA(v[0], v[1]); cexD(v[2], v[3]); cexA(v[4], v[5]); cexD(v[6], v[7]);
    cexA(v[0], v[2]); cexA(v[1], v[3]); cexD(v[4], v[6]); cexD(v[5], v[7]);
    cexA(v[0], v[1]); cexA(v[2], v[3]); cexD(v[4], v[5]); cexD(v[6], v[7]);
    bool a8 = (lane & 1) == 0;
    merge8(v, a8);
    bool a16 = (lane & 2) == 0;
    cross8(v, 1, ((lane & 1) == 0) == a16);
    merge8(v, a16);
    bool a32 = (lane & 4) == 0;
    cross8(v, 2, ((lane & 2) == 0) == a32);
    cross8(v, 1, ((lane & 1) == 0) == a32);
    merge8(v, a32);
    bool a64 = (lane & 8) == 0;
    cross8(v, 4, ((lane & 4) == 0) == a64);
    cross8(v, 2, ((lane & 2) == 0) == a64);
    cross8(v, 1, ((lane & 1) == 0) == a64);
    merge8(v, a64);
    bool a128 = (lane & 16) == 0;
    cross8(v, 8, ((lane & 8) == 0) == a128);
    cross8(v, 4, ((lane & 4) == 0) == a128);
    cross8(v, 2, ((lane & 2) == 0) == a128);
    cross8(v, 1, ((lane & 1) == 0) == a128);
    merge8(v, a128);
    cross8(v, 16, (lane & 16) == 0);
    cross8(v, 8,  (lane & 8) == 0);
    cross8(v, 4,  (lane & 4) == 0);
    cross8(v, 2,  (lane & 2) == 0);
    cross8(v, 1,  (lane & 1) == 0);
    merge8(v, true);
}

__device__ __forceinline__ float2 blockReduceSum2_256(float2 val, float2* sbuf) {
    int tid = threadIdx.x;
#pragma unroll
    for (int o = 16; o > 0; o >>= 1) {
        val.x += __shfl_down_sync(0xffffffffu, val.x, o);
        val.y += __shfl_down_sync(0xffffffffu, val.y, o);
    }
    if ((tid & 31) == 0) sbuf[tid >> 5] = val;
    __syncthreads();
    if (tid < 32) {
        float2 r = (tid < 8) ? sbuf[tid] : make_float2(0.f, 0.f);
#pragma unroll
        for (int o = 4; o > 0; o >>= 1) {
            r.x += __shfl_down_sync(0xffffffffu, r.x, o);
            r.y += __shfl_down_sync(0xffffffffu, r.y, o);
        }
        if (tid == 0) sbuf[32] = r;
    }
    __syncthreads();
    float2 out = sbuf[32];
    __syncthreads();
    return out;
}

// ===== MEGA: k1 (0..383) + k3 (384..2431) + k4a (2432..3071, gated) + k5 (3072.., gated) =====
#define FK_SMEM 18432
#define NK1 384
#define NK3 2048
#define NK4 640
#define NPROD (NK3 + NK4)

__global__ void __launch_bounds__(256) mega(const float* __restrict__ H,
                                            const int* __restrict__ tt,
                                            const int* __restrict__ m,
                                            const float* __restrict__ Wc,
                                            const float* __restrict__ Ws,
                                            const float* __restrict__ bc,
                                            const float* __restrict__ bs,
                                            const float* __restrict__ gate,
                                            const float* __restrict__ ln_g,
                                            const float* __restrict__ ln_b,
                                            const float* __restrict__ Wcls,
                                            const float* __restrict__ bcls,
                                            float* __restrict__ out) {
    extern __shared__ char dyn[];
    int tid = threadIdx.x;

    if (blockIdx.x < NK1) {
        // ---------------- k1 role: masked means + cls -> g_rep ----------------
        int bid = blockIdx.x;
        int b = bid / 3, c = bid % 3;
        float* sf0 = reinterpret_cast<float*>(dyn);       // 256
        float* sf1 = sf0 + 256;                           // 256
        float* red = sf1 + 256;                           // [256][8]
        __shared__ float cbuf[2][8];

        int t = tt[b * Lx + tid];
        int mm = m[b * Lx + tid];
        float f0 = (t == 0 && mm == 1) ? 1.f : 0.f;
        float f1 = (t == 1 && mm == 1) ? 1.f : 0.f;
        sf0[tid] = f0;
        sf1[tid] = f1;
        // block count reduce
        float w0 = f0, w1 = f1;
#pragma unroll
        for (int o = 16; o > 0; o >>= 1) {
            w0 += __shfl_down_sync(0xffffffffu, w0, o);
            w1 += __shfl_down_sync(0xffffffffu, w1, o);
        }
        if ((tid & 31) == 0) { cbuf[0][tid >> 5] = w0; cbuf[1][tid >> 5] = w1; }
        __syncthreads();

        float c0 = 0.f, c1 = 0.f;
#pragma unroll
        for (int q = 0; q < 8; q++) { c0 += cbuf[0][q]; c1 += cbuf[1][q]; }
        float ic0 = 1.f / fmaxf(c0, 1.f);
        float ic1 = 1.f / fmaxf(c1, 1.f);

        int h4 = tid & 63;                 // float4 col within 256-h chunk
        int lq = tid >> 6;                 // l quarter
        const float* Hb = H + (size_t)b * Lx * HIDx + c * 256 + h4 * 4;

        float a0 = 0.f, a1 = 0.f, a2 = 0.f, a3 = 0.f;
        float d0 = 0.f, d1 = 0.f, d2 = 0.f, d3 = 0.f;
        int lbase = lq * 64;
#pragma unroll 8
        for (int li = 0; li < 64; li++) {
            int l = lbase + li;
            float4 v = *reinterpret_cast<const float4*>(Hb + (size_t)l * HIDx);
            float u0 = sf0[l], u1 = sf1[l];
            a0 += u0 * v.x; d0 += u1 * v.x;
            a1 += u0 * v.y; d1 += u1 * v.y;
            a2 += u0 * v.z; d2 += u1 * v.z;
            a3 += u0 * v.w; d3 += u1 * v.w;
        }
        float* rr = red + (size_t)tid * 8;
        rr[0] = a0; rr[1] = a1; rr[2] = a2; rr[3] = a3;
        rr[4] = d0; rr[5] = d1; rr[6] = d2; rr[7] = d3;
        __syncthreads();

        if (lq == 0) {
            float s0[4] = {0.f, 0.f, 0.f, 0.f}, s1[4] = {0.f, 0.f, 0.f, 0.f};
#pragma unroll
            for (int q = 0; q < 4; q++) {
                float* rq = red + (size_t)(q * 64 + h4) * 8;
#pragma unroll
                for (int j = 0; j < 4; j++) { s0[j] += rq[j]; s1[j] += rq[4 + j]; }
            }
            int h = c * 256 + h4 * 4;
            float4 cls = *reinterpret_cast<const float4*>(H + (size_t)b * Lx * HIDx + h);
            *reinterpret_cast<float4*>(&g_rep[(size_t)b * HID2x + h]) = cls;
            float4 md = make_float4(s0[0] * ic0 - s1[0] * ic1,
                                    s0[1] * ic0 - s1[1] * ic1,
                                    s0[2] * ic0 - s1[2] * ic1,
                                    s0[3] * ic0 - s1[3] * ic1);
            *reinterpret_cast<float4*>(&g_rep[(size_t)b * HID2x + HIDx + h]) = md;
        }
        __threadfence();
        __syncthreads();
        if (tid == 0) atomicAdd(&g_repdone, 1);
    } else if (blockIdx.x < NK1 + NK3) {
        // ---------------- k3: sort role (independent of k1) ----------------
        int bid = blockIdx.x - NK1;
        int b = bid >> 4;
        int px = bid & 15;
        int warp = tid >> 5, lane = tid & 31;
        float* sgrp = reinterpret_cast<float*>(dyn);

        int p = px * 8 + warp;
        const float* col = g_Pt + ((size_t)b * NPROJx + p) * Lx;

        float4 va = reinterpret_cast<const float4*>(col)[lane * 2];
        float4 vb = reinterpret_cast<const float4*>(col)[lane * 2 + 1];
        int4 ta = reinterpret_cast<const int4*>(tt + b * Lx)[lane * 2];
        int4 tb = reinterpret_cast<const int4*>(tt + b * Lx)[lane * 2 + 1];
        int4 ma = reinterpret_cast<const int4*>(m + b * Lx)[lane * 2];
        int4 mb = reinterpret_cast<const int4*>(m + b * Lx)[lane * 2 + 1];

        float raw[8] = {va.x, va.y, va.z, va.w, vb.x, vb.y, vb.z, vb.w};
        int tvs[8] = {ta.x, ta.y, ta.z, ta.w, tb.x, tb.y, tb.z, tb.w};
        int mvs[8] = {ma.x, ma.y, ma.z, ma.w, mb.x, mb.y, mb.z, mb.w};

        // local mcnt (no dependency on k1)
        int cnt0 = 0, cnt1 = 0;
        float v[8];
#pragma unroll
        for (int r = 0; r < 8; r++) {
            int tg = (mvs[r] == 1) ? tvs[r] : 2;
            cnt0 += (tg == 0);
            cnt1 += (tg == 1);
            float base = (tg == 2) ? BIGF : raw[r];
            uint32_t u = (__float_as_uint(base) & ~1u) | (uint32_t)(tg != 0);
            v[r] = __uint_as_float(u);
        }
        int c0t = __reduce_add_sync(0xffffffffu, cnt0);
        int c1t = __reduce_add_sync(0xffffffffu, cnt1);
        int mc = min(c0t, c1t);

        sort256v2(v, lane);

        int g[8];
        int cl = 0;
#pragma unroll
        for (int r = 0; r < 8; r++) {
            g[r] = (int)(__float_as_uint(v[r]) & 1u);
            cl += g[r];
        }
        int inc = cl;
#pragma unroll
        for (int o = 1; o < 32; o <<= 1) {
            int n = __shfl_up_sync(0xffffffffu, inc, o);
            if (lane >= o) inc += n;
        }
        int c1 = inc - cl;

        float* s0 = sgrp + warp * 512;
        float* s1 = s0 + 256;
#pragma unroll
        for (int r = 0; r < 8; r++) {
            float val = __uint_as_float(__float_as_uint(v[r]) & ~1u);
            int idx = lane * 8 + r;
            if (g[r]) { s1[c1] = val; c1++; }
            else      { s0[idx - c1] = val; }
        }
        __syncwarp();

        float s = 0.f;
#pragma unroll
        for (int r = 0; r < 8; r++) {
            int i = r * 32 + lane;
            if (i < mc) s += fabsf(s0[i] - s1[i]);
        }
#pragma unroll
        for (int o = 16; o > 0; o >>= 1) s += __shfl_down_sync(0xffffffffu, s, o);

        if (lane == 0) {
            float mean = s / (float)max(mc, 1);
            atomicMax(reinterpret_cast<int*>(&g_feat[b * FDIMx + 320]), __float_as_int(mean));
        }
        __threadfence();
        __syncthreads();
        if (tid == 0) atomicAdd(&g_done, 1);
    } else if (blockIdx.x < NK1 + NK3 + NK4) {
        // ---------------- k4a: feature GEMM role (gated on k1) ----------------
        if (tid == 0) {
            volatile int* dp = &g_repdone;
            while (*dp < NK1) { }
        }
        __syncthreads();
        __threadfence();

        int idx = blockIdx.x - (NK1 + NK3);
        int ftile = (idx % 5) * 64;
        int btile = ((idx / 5) & 3) * 32;
        int kc    = (idx / 20) * 48;

        float* repS = reinterpret_cast<float*>(dyn);
        float* wS   = repS + 48 * 32;

        int tx = tid & 15;
        int ty = tid >> 4;

#pragma unroll
        for (int s = 0; s < 3; s++) {
#pragma unroll
            for (int q = 0; q < 2; q++) {
                int e = tid + q * 256;
                int kk = e & 15, bb = e >> 4;
                repS[(s * 16 + kk) * 32 + bb] = g_rep[(size_t)(btile + bb) * HID2x + kc + s * 16 + kk];
            }
#pragma unroll
            for (int q = 0; q < 4; q++) {
                int e = tid + q * 256;
                int kk = e & 15, ff = e >> 4;
                int f = ftile + ff;
                const float* Wr = (f < CDIMx) ? (Wc + (size_t)f * HID2x)
                                              : (Ws + (size_t)(f - CDIMx) * HID2x);
                wS[(s * 16 + kk) * 64 + ff] = Wr[kc + s * 16 + kk];
            }
        }
        __syncthreads();

        float acc[2][4];
#pragma unroll
        for (int i = 0; i < 2; i++)
#pragma unroll
            for (int j = 0; j < 4; j++) acc[i][j] = 0.f;

#pragma unroll 8
        for (int kk = 0; kk < 48; kk++) {
            float4 wv = *reinterpret_cast<const float4*>(&wS[kk * 64 + tx * 4]);
            float r0 = repS[kk * 32 + ty * 2];
            float r1 = repS[kk * 32 + ty * 2 + 1];
            acc[0][0] += r0 * wv.x; acc[0][1] += r0 * wv.y;
            acc[0][2] += r0 * wv.z; acc[0][3] += r0 * wv.w;
            acc[1][0] += r1 * wv.x; acc[1][1] += r1 * wv.y;
            acc[1][2] += r1 * wv.z; acc[1][3] += r1 * wv.w;
        }

        int z = idx / 20;
#pragma unroll
        for (int i = 0; i < 2; i++) {
            int bb = btile + ty * 2 + i;
            float4 o = make_float4(acc[i][0], acc[i][1], acc[i][2], acc[i][3]);
            *reinterpret_cast<float4*>(&g_partial[((size_t)z * Bx + bb) * 320 + ftile + tx * 4]) = o;
        }
        __threadfence();
        __syncthreads();
        if (tid == 0) atomicAdd(&g_done, 1);
    } else {
        // ---------------- k5 role: wait for all producers, then LN + classifier ----------------
        int b = blockIdx.x - (NK1 + NK3 + NK4);
        float2* sbuf = reinterpret_cast<float2*>(dyn);

        if (tid == 0) {
            volatile int* dp = &g_done;
            while (*dp < NPROD) { }
        }
        __syncthreads();
        __threadfence();

        float gv = 1.f / (1.f + expf(-gate[0]));

        int f1 = tid;
        int f2 = tid + 256;
        float x1 = 0.f, x2 = 0.f;
        {
            float s = 0.f;
#pragma unroll
            for (int z = 0; z < 32; z++) s += g_partial[((size_t)z * Bx + b) * 320 + f1];
            if (f1 < CDIMx) x1 = (s + bc[f1]) * (1.f - gv);
            else            x1 = (s + bs[f1 - CDIMx]) * gv;
        }
        if (f2 < 320) {
            float s = 0.f;
#pragma unroll
            for (int z = 0; z < 32; z++) s += g_partial[((size_t)z * Bx + b) * 320 + f2];
            x2 = (s + bs[f2 - CDIMx]) * gv;
        } else if (f2 == 320) {
            x2 = g_feat[b * FDIMx + 320];
        }

        float2 ss = blockReduceSum2_256(make_float2(x1 + x2, x1 * x1 + x2 * x2), sbuf);
        float mean = ss.x / (float)FDIMx;
        float var  = ss.y / (float)FDIMx - mean * mean;
        float inv  = rsqrtf(var + 1e-5f);

        float nrm1 = (x1 - mean) * inv * ln_g[f1] + ln_b[f1];
        float cc0 = nrm1 * Wcls[f1];
        float cc1 = nrm1 * Wcls[FDIMx + f1];
        if (f2 <= 320) {
            float nrm2 = (x2 - mean) * inv * ln_g[f2] + ln_b[f2];
            cc0 += nrm2 * Wcls[f2];
            cc1 += nrm2 * Wcls[FDIMx + f2];
        }

        float2 cls = blockReduceSum2_256(make_float2(cc0, cc1), sbuf);
        if (tid == 0) {
            out[b * 2 + 0] = cls.x + bcls[0];
            out[b * 2 + 1] = cls.y + bcls[1];
        }
    }
}

// =================================== launch ======================================
extern "C" void kernel_launch(void* const* d_in, const int* in_sizes, int n_in,
                              void* d_out, int out_size) {
    const float* H    = (const float*)d_in[0];
    const int*   tt   = (const int*)d_in[1];
    const int*   m    = (const int*)d_in[2];
    const float* Wc   = (const float*)d_in[3];
    const float* bc   = (const float*)d_in[4];
    const float* Ws   = (const float*)d_in[5];
    const float* bs   = (const float*)d_in[6];
    const float* gate = (const float*)d_in[7];
    const float* ln_g = (const float*)d_in[8];
    const float* ln_b = (const float*)d_in[9];
    const float* Wcls = (const float*)d_in[10];
    const float* bcls = (const float*)d_in[11];
    const float* proj = (const float*)d_in[12];
    float* out = (float*)d_out;

    cudaFuncSetAttribute(k2_hmma, cudaFuncAttributeMaxDynamicSharedMemorySize, K2_SMEM);

    k0_prep<<<96, 256>>>(proj);
    k2_hmma<<<dim3(Bx, 2), 256, K2_SMEM>>>(H);
    mega<<<NK1 + NK3 + NK4 + Bx, 256, FK_SMEM>>>(H, tt, m, Wc, Ws, bc, bs, gate,
                                                 ln_g, ln_b, Wcls, bcls, out);
}